// round 2
// baseline (speedup 1.0000x reference)
#include <cuda_runtime.h>

// Who2com reduces algebraically to mean over the N (agent) axis:
//   out[b,c,h,w] = (1/N) * sum_n bevs[b,n,c,h,w]
// (softmax columns sum to 1; val_mat is broadcast over the key axis).
//
// B=32, N=5, C=256, H=W=16.  CHW4 = 16384 float4 per (b,n) slice.
// Each thread handles 2 float4 (10 loads + 2 stores in flight).
// Tile per block = 512 float4 -> 32 tiles per b-slice (exact), 1024 blocks.

static constexpr int B_   = 32;
static constexpr int N_   = 5;
static constexpr int CHW4 = 256 * 16 * 16 / 4;   // 16384
static constexpr int PER_THREAD = 2;
static constexpr int TILE = 256 * PER_THREAD;    // 512 float4 per block
static constexpr int NBLOCKS = B_ * CHW4 / TILE; // 1024

__global__ __launch_bounds__(256) void who2com_mean_kernel(
    const float4* __restrict__ bevs, float4* __restrict__ out)
{
    int tile_base = blockIdx.x * TILE;         // global float4 index of tile
    int b   = tile_base >> 14;                 // tile fully inside one b-slice
    int chw0 = (tile_base & (CHW4 - 1)) + threadIdx.x;

    const float4* base = bevs + (size_t)b * N_ * CHW4;
    float4* obase = out + (size_t)b * CHW4;

    float4 a[PER_THREAD][N_];
#pragma unroll
    for (int u = 0; u < PER_THREAD; u++) {
        int chw = chw0 + u * 256;
#pragma unroll
        for (int n = 0; n < N_; n++)
            a[u][n] = __ldcs(base + n * CHW4 + chw);
    }

    const float inv_n = 0.2f;
#pragma unroll
    for (int u = 0; u < PER_THREAD; u++) {
        int chw = chw0 + u * 256;
        float4 r;
        r.x = (a[u][0].x + a[u][1].x + a[u][2].x + a[u][3].x + a[u][4].x) * inv_n;
        r.y = (a[u][0].y + a[u][1].y + a[u][2].y + a[u][3].y + a[u][4].y) * inv_n;
        r.z = (a[u][0].z + a[u][1].z + a[u][2].z + a[u][3].z + a[u][4].z) * inv_n;
        r.w = (a[u][0].w + a[u][1].w + a[u][2].w + a[u][3].w + a[u][4].w) * inv_n;
        __stcs(obase + chw, r);
    }
}

extern "C" void kernel_launch(void* const* d_in, const int* in_sizes, int n_in,
                              void* d_out, int out_size)
{
    const float4* bevs = (const float4*)d_in[0];  // (B, N, C, H, W) fp32
    float4* out = (float4*)d_out;                 // (B, C, H, W) fp32
    who2com_mean_kernel<<<NBLOCKS, 256>>>(bevs, out);
}